// round 11
// baseline (speedup 1.0000x reference)
#include <cuda_runtime.h>
#include <cuda_bf16.h>
#include <cstdint>

#define NN   100000
#define TILE 128

// ---- scratch (allocation-free rule: __device__ globals) ----
__device__ float g_kyv[NN * 64];            // K1 output ky_v
__device__ float g_acc[NN * 64];            // scatter accumulator
__device__ float g_cnt[NN];                 // scatter counts
__device__ uint32_t g_Bhi[2][16][2048];     // prepacked W2 hi bf16 pairs [kid][c*4+g][col*32+m2]
__device__ uint32_t g_Blo[2][16][2048];     // prepacked W2 lo

// ============================================================================
// helpers
// ============================================================================
__device__ __forceinline__ uint32_t smem_u32(const void* p) {
    uint32_t a;
    asm("{ .reg .u64 t; cvta.to.shared.u64 t, %1; cvt.u32.u64 %0, t; }" : "=r"(a) : "l"(p));
    return a;
}
__device__ __forceinline__ void split_pack(float v0, float v1, uint32_t& hiw, uint32_t& low) {
    __nv_bfloat16 h0 = __float2bfloat16(v0), h1 = __float2bfloat16(v1);
    __nv_bfloat16 l0 = __float2bfloat16(v0 - __bfloat162float(h0));
    __nv_bfloat16 l1 = __float2bfloat16(v1 - __bfloat162float(h1));
    hiw = (uint32_t)__bfloat16_as_ushort(h0) | ((uint32_t)__bfloat16_as_ushort(h1) << 16);
    low = (uint32_t)__bfloat16_as_ushort(l0) | ((uint32_t)__bfloat16_as_ushort(l1) << 16);
}
__device__ __forceinline__ void lda4(uint32_t* r, uint32_t addr) {
    asm volatile("ldmatrix.sync.aligned.m8n8.x4.shared.b16 {%0,%1,%2,%3}, [%4];"
        : "=r"(r[0]), "=r"(r[1]), "=r"(r[2]), "=r"(r[3]) : "r"(addr));
}
__device__ __forceinline__ void ldb4(uint32_t* r, uint32_t addr) {
    asm volatile("ldmatrix.sync.aligned.m8n8.x4.shared.b16 {%0,%1,%2,%3}, [%4];"
        : "=r"(r[0]), "=r"(r[1]), "=r"(r[2]), "=r"(r[3]) : "r"(addr));
}
__device__ __forceinline__ void mma16816(float* c, const uint32_t* a, const uint32_t* b) {
    asm volatile("mma.sync.aligned.m16n8k16.row.col.f32.bf16.bf16.f32 "
        "{%0,%1,%2,%3}, {%4,%5,%6,%7}, {%8,%9}, {%0,%1,%2,%3};"
        : "+f"(c[0]), "+f"(c[1]), "+f"(c[2]), "+f"(c[3])
        : "r"(a[0]), "r"(a[1]), "r"(a[2]), "r"(a[3]), "r"(b[0]), "r"(b[1]));
}
__device__ __forceinline__ void cp16(uint32_t d, const void* s) {
    asm volatile("cp.async.ca.shared.global [%0], [%1], 16;" :: "r"(d), "l"(s));
}
#define CP_COMMIT() asm volatile("cp.async.commit_group;" ::: "memory")
#define CP_WAIT0()  asm volatile("cp.async.wait_group 0;"  ::: "memory")

// smem layout (bytes). A/B rows 144B (16B-aligned for ldmatrix; 144 mod 128 = 16
// -> conflict-free). After A-frag load, [0..34816) is dead: K2 stages v there
// (pitch 68 f32). Tail reuses O_BUF for mW^T (pitch 68 f32, 17408B).
// 73728 x 3 CTAs = 221184 B fits the 228KB carveout -> 3 CTAs/SM.
enum { O_AHI = 0,                       // H hi : 128 x 144 = 18432
       O_ALO = 18432,                   // H lo : 128 x 144
       O_BUF = 36864,                   // 2 x (Bt hi 9216 + Bt lo 9216) = 36864
       SMEM_SZ = 73728 };

// ============================================================================
// prep: W2 -> bf16 hi/lo, ldmatrix tile layout [col][m2]. 32 blocks, ~5us.
// ============================================================================
__global__ __launch_bounds__(256)
void prep_kernel(const float* __restrict__ W2a, const float* __restrict__ W2b)
{
    const int b = blockIdx.x;              // 0..31
    const int k = b >> 4, t = b & 15;
    const int c = t >> 2, g = t & 3;
    const float* W2 = k ? W2b : W2a;
    const int tid = threadIdx.x;
    #pragma unroll
    for (int it = 0; it < 8; it++) {
        int p = tid + it * 256;            // 2048
        int col = p & 63, m2 = p >> 6;
        float w0 = W2[(size_t)(2 * m2)     * 1024 + c * 256 + g * 64 + col];
        float w1 = W2[(size_t)(2 * m2 + 1) * 1024 + c * 256 + g * 64 + col];
        uint32_t hi, lo;
        split_pack(w0, w1, hi, lo);
        g_Bhi[k][t][col * 32 + m2] = hi;
        g_Blo[k][t][col * 32 + m2] = lo;
    }
}

// ============================================================================
// Fused node kernel (round-10 structure, 3 CTAs/SM).  A hi/lo frags in
// registers (loaded once, A smem dead after); B double-buffered via cp.async;
// ct tiles in two halves of 4 (acc = 16 live regs); b2 read via __ldg (L1).
// K1 -> g_kyv (+zero acc/cnt).  K2: v -> dead A smem region, mix Linear tail.
// ============================================================================
template<int IS_K2>
__global__ __launch_bounds__(256, 3)
void node_kernel(const float* __restrict__ xin, const float* __restrict__ ea,
                 const float* __restrict__ W1, const float* __restrict__ b1,
                 const float* __restrict__ b2,
                 const float* __restrict__ mW, const float* __restrict__ mb,
                 float* __restrict__ out, int n)
{
    extern __shared__ __align__(16) char sm[];
    const uint32_t smb = smem_u32(sm);
    const int tid = threadIdx.x, wid = tid >> 5, lane = tid & 31;
    const int nb = blockIdx.x * TILE;

    // ---- stage A: h = relu(ea@W1+b1) hi/lo bf16, [node][m], row 144B ----
    {
        const int node = tid >> 1, mh = tid & 1;
        const bool ok = (nb + node) < n;
        float e0 = 0.f, e1 = 0.f, e2 = 0.f;
        if (ok) { const float* e = ea + (size_t)(nb + node) * 3; e0 = e[0]; e1 = e[1]; e2 = e[2]; }
        #pragma unroll
        for (int mm = 0; mm < 16; mm++) {
            int m = mh * 32 + mm * 2;
            float h0 = 0.f, h1 = 0.f;
            if (ok) {
                h0 = fmaxf(fmaf(e2, W1[128 + m],     fmaf(e1, W1[64 + m],     fmaf(e0, W1[m],     b1[m]))),     0.f);
                h1 = fmaxf(fmaf(e2, W1[128 + m + 1], fmaf(e1, W1[64 + m + 1], fmaf(e0, W1[m + 1], b1[m + 1]))), 0.f);
            }
            uint32_t hiw, low;
            split_pack(h0, h1, hiw, low);
            uint32_t off = (uint32_t)(node * 144 + m * 2);
            *(uint32_t*)(sm + O_AHI + off) = hiw;
            *(uint32_t*)(sm + O_ALO + off) = low;
        }
    }
    // ---- K1: zero scatter accumulators for this tile ----
    if (!IS_K2) {
        const float4 z4 = make_float4(0.f, 0.f, 0.f, 0.f);
        #pragma unroll
        for (int i = 0; i < 8; i++) {
            int idx4 = tid + i * 256;
            int node = idx4 >> 4;
            if (nb + node < n) ((float4*)g_acc)[(size_t)nb * 16 + idx4] = z4;
        }
        if (tid < TILE && nb + tid < n) g_cnt[nb + tid] = 0.f;
    }
    __syncthreads();                               // A staged

    // ---- load A fragments ONCE (A smem region dead afterwards) ----
    const uint32_t aRow = (uint32_t)((wid * 16 + (lane & 15)) * 144 + ((lane >> 4) * 16));
    uint32_t ah[4][4], al[4][4];
    #pragma unroll
    for (int ks = 0; ks < 4; ks++) {
        lda4(ah[ks], smb + O_AHI + aRow + ks * 32);
        lda4(al[ks], smb + O_ALO + aRow + ks * 32);
    }

    // x4 B addressing: lanes 16-31 take the next ct tile (+8 rows = +1152B)
    const uint32_t bRow4 = (uint32_t)((lane & 7) * 144 + (((lane >> 3) & 1) * 16)
                                      + ((lane >> 4) * 1152));
    const int r0   = wid * 16 + (lane >> 2);       // C frag rows r0, r0+8
    const int colq = 2 * (lane & 3);

    const int row0 = nb + r0, row1 = nb + r0 + 8;
    const bool v0 = row0 < n, v1 = row1 < n;
    const float* src = IS_K2 ? g_acc : xin;
    float inv0 = 1.f, inv1 = 1.f;
    if (IS_K2) {
        if (v0) inv0 = 1.0f / fmaxf(g_cnt[row0], 1.0f);
        if (v1) inv1 = 1.0f / fmaxf(g_cnt[row1], 1.0f);
    }

    // per-thread cp.async slots (same tile mapping as prep layout)
    const uint32_t st_off0 = (uint32_t)((tid >> 3) * 144 + (tid & 7) * 16);
    const uint32_t st_off1 = (uint32_t)(((tid + 256) >> 3) * 144 + (tid & 7) * 16);

    // ---- prologue: stage tile q=0 into buf 0 ----
    {
        const char* sH = (const char*)g_Bhi[IS_K2][0];
        const char* sL = (const char*)g_Blo[IS_K2][0];
        uint32_t dH = smb + O_BUF;
        cp16(dH + st_off0,        sH + (size_t)tid * 16);
        cp16(dH + 9216 + st_off0, sL + (size_t)tid * 16);
        cp16(dH + st_off1,        sH + (size_t)(tid + 256) * 16);
        cp16(dH + 9216 + st_off1, sL + (size_t)(tid + 256) * 16);
        CP_COMMIT();
    }

    for (int c = 0; c < 4; c++) {
        float y[8] = {0.f, 0.f, 0.f, 0.f, 0.f, 0.f, 0.f, 0.f};

        for (int gg = 0; gg < 4; gg++) {
            const int q = c * 4 + gg;
            CP_WAIT0();
            __syncthreads();                       // buf q ready; buf q+1 free
            if (q < 15) {                          // async-stage next tile
                const char* sH = (const char*)g_Bhi[IS_K2][q + 1];
                const char* sL = (const char*)g_Blo[IS_K2][q + 1];
                uint32_t dH = smb + O_BUF + ((q + 1) & 1) * 18432;
                cp16(dH + st_off0,        sH + (size_t)tid * 16);
                cp16(dH + 9216 + st_off0, sL + (size_t)tid * 16);
                cp16(dH + st_off1,        sH + (size_t)(tid + 256) * 16);
                cp16(dH + 9216 + st_off1, sL + (size_t)(tid + 256) * 16);
                CP_COMMIT();
            }

            // x for phase B (load early; read-only data)
            float4 x0 = make_float4(0.f, 0.f, 0.f, 0.f), x1 = x0;
            if (v0) x0 = *(const float4*)&src[(size_t)row0 * 64 + c * 16 + gg * 4];
            if (v1) x1 = *(const float4*)&src[(size_t)row1 * 64 + c * 16 + gg * 4];
            float xk0a[4] = {x0.x, x0.y, x0.z, x0.w};
            float xk1a[4] = {x1.x, x1.y, x1.z, x1.w};

            const uint32_t bufb = smb + O_BUF + (uint32_t)((q & 1) * 18432);

            // ---- HMMA in two ct-halves (acc = 16 regs each) ----
            #pragma unroll
            for (int h = 0; h < 2; h++) {
                float acc[4][4];
                #pragma unroll
                for (int l = 0; l < 4; l++)
                    #pragma unroll
                    for (int p = 0; p < 4; p++) acc[l][p] = 0.f;
                #pragma unroll
                for (int ks = 0; ks < 4; ks++) {
                    #pragma unroll
                    for (int c2 = 0; c2 < 2; c2++) {
                        uint32_t bq[4];
                        ldb4(bq, bufb + (uint32_t)((h * 4 + c2 * 2) * 1152) + bRow4 + ks * 32);
                        mma16816(acc[c2 * 2],     ah[ks], bq);
                        mma16816(acc[c2 * 2 + 1], ah[ks], bq + 2);
                        mma16816(acc[c2 * 2],     al[ks], bq);
                        mma16816(acc[c2 * 2 + 1], al[ks], bq + 2);
                    }
                    #pragma unroll
                    for (int c2 = 0; c2 < 2; c2++) {
                        uint32_t bq[4];
                        ldb4(bq, bufb + 9216u + (uint32_t)((h * 4 + c2 * 2) * 1152) + bRow4 + ks * 32);
                        mma16816(acc[c2 * 2],     ah[ks], bq);
                        mma16816(acc[c2 * 2 + 1], ah[ks], bq + 2);
                    }
                }
                // ---- phase B for this half (b2 via __ldg, L1-resident) ----
                #pragma unroll
                for (int l = 0; l < 4; l++) {
                    const int ct = h * 4 + l;
                    const int kl = ct >> 1;
                    const int jb = (ct & 1) * 2;
                    float2 bb = __ldg((const float2*)&b2[c * 256 + gg * 64 + ct * 8 + colq]);
                    y[jb]         = fmaf(xk0a[kl], acc[l][0] + bb.x, y[jb]);
                    y[jb + 1]     = fmaf(xk0a[kl], acc[l][1] + bb.y, y[jb + 1]);
                    y[4 + jb]     = fmaf(xk1a[kl], acc[l][2] + bb.x, y[4 + jb]);
                    y[4 + jb + 1] = fmaf(xk1a[kl], acc[l][3] + bb.y, y[4 + jb + 1]);
                }
            }
        }

        if (!IS_K2) {
            if (v0) {
                *(float2*)&g_kyv[(size_t)row0 * 64 + c * 16 + colq]     = make_float2(y[0], y[1]);
                *(float2*)&g_kyv[(size_t)row0 * 64 + c * 16 + 8 + colq] = make_float2(y[2], y[3]);
            }
            if (v1) {
                *(float2*)&g_kyv[(size_t)row1 * 64 + c * 16 + colq]     = make_float2(y[4], y[5]);
                *(float2*)&g_kyv[(size_t)row1 * 64 + c * 16 + 8 + colq] = make_float2(y[6], y[7]);
            }
        } else {
            // v -> dead A smem region, pitch 68 floats (272B/row), mean folded
            char* vr0 = sm + r0 * 272 + (c * 16 + colq) * 4;
            char* vr1 = sm + (r0 + 8) * 272 + (c * 16 + colq) * 4;
            *(float2*)vr0        = make_float2(y[0] * inv0, y[1] * inv0);
            *(float2*)(vr0 + 32) = make_float2(y[2] * inv0, y[3] * inv0);
            *(float2*)vr1        = make_float2(y[4] * inv1, y[5] * inv1);
            *(float2*)(vr1 + 32) = make_float2(y[6] * inv1, y[7] * inv1);
        }
    }

    // ---- K2 tail: out = v @ mW^T + mb.  v in smem [0..34816), mW^T -> O_BUF.
    if (IS_K2) {
        __syncthreads();                           // v writes + B reads done
        #pragma unroll
        for (int it = 0; it < 16; it++) {
            int p = tid + it * 256;                // 4096
            int j = p >> 6, i = p & 63;
            *(float*)(sm + O_BUF + (j * 68 + i) * 4) = mW[(size_t)i * 64 + j];
        }
        __syncthreads();
        const int node_b = tid >> 1, jh = tid & 1;
        if (nb + node_b < n) {
            float a[32];
            #pragma unroll
            for (int p = 0; p < 8; p++) {
                float4 m4 = ((const float4*)mb)[jh * 8 + p];
                a[p*4] = m4.x; a[p*4+1] = m4.y; a[p*4+2] = m4.z; a[p*4+3] = m4.w;
            }
            #pragma unroll 4
            for (int j = 0; j < 64; j++) {
                float vj = *(const float*)(sm + (node_b * 68 + j) * 4);
                #pragma unroll
                for (int p = 0; p < 8; p++) {
                    float4 w = *(const float4*)(sm + O_BUF + (j * 68 + jh * 32 + p * 4) * 4);
                    a[p*4]   = fmaf(vj, w.x, a[p*4]);
                    a[p*4+1] = fmaf(vj, w.y, a[p*4+1]);
                    a[p*4+2] = fmaf(vj, w.z, a[p*4+2]);
                    a[p*4+3] = fmaf(vj, w.w, a[p*4+3]);
                }
            }
            float* dst = &out[(size_t)(nb + node_b) * 64 + jh * 32];
            #pragma unroll
            for (int p = 0; p < 8; p++)
                ((float4*)dst)[p] = make_float4(a[p*4], a[p*4+1], a[p*4+2], a[p*4+3]);
        }
    }
}

// ============================================================================
// Edge scatter: acc[dst] += ky_v[src], cnt[dst] += 1.  float4 vector atomics.
// ============================================================================
__global__ __launch_bounds__(256)
void scatter_kernel(const int* __restrict__ ei, int n_edges)
{
    __shared__ int s_dst[256];
    __shared__ int s_src[256];
    const int tid  = threadIdx.x;
    const int base = blockIdx.x * 256;
    const int nE   = min(256, n_edges - base);
    if (nE <= 0) return;

    if (tid < nE) {
        s_dst[tid] = ei[base + tid];
        s_src[tid] = ei[n_edges + base + tid];
    }
    __syncthreads();

    const int w = tid >> 5, lane = tid & 31;
    const int half16 = lane >> 4, l16 = lane & 15;

    #pragma unroll 4
    for (int p = 0; p < 16; p++) {
        int le = w * 32 + p * 2 + half16;
        if (le < nE) {
            int src = s_src[le];
            int dst = s_dst[le];
            float4 v = *(const float4*)&g_kyv[(size_t)src * 64 + l16 * 4];
            atomicAdd((float4*)&g_acc[(size_t)dst * 64 + l16 * 4], v);
            if (l16 == 0) atomicAdd(&g_cnt[dst], 1.0f);
        }
    }
}

// ============================================================================
extern "C" void kernel_launch(void* const* d_in, const int* in_sizes, int n_in,
                              void* d_out, int out_size)
{
    const float* x    = (const float*)d_in[0];
    const float* ea   = (const float*)d_in[1];
    const int*   ei   = (const int*)  d_in[2];
    const float* k1W1 = (const float*)d_in[3];
    const float* k1b1 = (const float*)d_in[4];
    const float* k1W2 = (const float*)d_in[5];
    const float* k1b2 = (const float*)d_in[6];
    const float* k2W1 = (const float*)d_in[7];
    const float* k2b1 = (const float*)d_in[8];
    const float* k2W2 = (const float*)d_in[9];
    const float* k2b2 = (const float*)d_in[10];
    const float* mW   = (const float*)d_in[11];
    const float* mb   = (const float*)d_in[12];
    float* out = (float*)d_out;

    const int n = in_sizes[0] / 64;        // 100000
    const int e = in_sizes[2] / 2;         // 3200000

    cudaFuncSetAttribute(node_kernel<0>, cudaFuncAttributeMaxDynamicSharedMemorySize, SMEM_SZ);
    cudaFuncSetAttribute(node_kernel<1>, cudaFuncAttributeMaxDynamicSharedMemorySize, SMEM_SZ);

    const int node_blocks = (n + TILE - 1) / TILE;
    const int edge_blocks = (e + 255) / 256;

    prep_kernel<<<32, 256>>>(k1W2, k2W2);
    node_kernel<0><<<node_blocks, 256, SMEM_SZ>>>(x, ea, k1W1, k1b1, k1b2,
                                                  nullptr, nullptr, nullptr, n);
    scatter_kernel<<<edge_blocks, 256>>>(ei, e);
    node_kernel<1><<<node_blocks, 256, SMEM_SZ>>>(nullptr, ea, k2W1, k2b1, k2b2,
                                                  mW, mb, out, n);
}

// round 12
// speedup vs baseline: 1.0680x; 1.0680x over previous
#include <cuda_runtime.h>
#include <cuda_bf16.h>
#include <cstdint>

#define NN   100000
#define EE   3200000
#define TILE 128

// ---- scratch (allocation-free rule: __device__ globals) ----
__device__ float g_kyv[NN * 64];            // K1 output ky_v
__device__ float g_acc[NN * 64];            // per-node message sums
__device__ float g_cnt[NN];                 // per-node degree (float)
__device__ uint32_t g_Bhi[2][16][2048];     // prepacked W2 hi bf16 pairs [kid][c*4+g][col*32+m2]
__device__ uint32_t g_Blo[2][16][2048];     // prepacked W2 lo
// CSR scratch
__device__ int g_hist[NN];
__device__ int g_rowptr[NN + 1];
__device__ int g_pos[NN];
__device__ int g_eidx[EE];
__device__ int g_bsum[512];

// ============================================================================
// helpers
// ============================================================================
__device__ __forceinline__ uint32_t smem_u32(const void* p) {
    uint32_t a;
    asm("{ .reg .u64 t; cvta.to.shared.u64 t, %1; cvt.u32.u64 %0, t; }" : "=r"(a) : "l"(p));
    return a;
}
__device__ __forceinline__ void split_pack(float v0, float v1, uint32_t& hiw, uint32_t& low) {
    __nv_bfloat16 h0 = __float2bfloat16(v0), h1 = __float2bfloat16(v1);
    __nv_bfloat16 l0 = __float2bfloat16(v0 - __bfloat162float(h0));
    __nv_bfloat16 l1 = __float2bfloat16(v1 - __bfloat162float(h1));
    hiw = (uint32_t)__bfloat16_as_ushort(h0) | ((uint32_t)__bfloat16_as_ushort(h1) << 16);
    low = (uint32_t)__bfloat16_as_ushort(l0) | ((uint32_t)__bfloat16_as_ushort(l1) << 16);
}
__device__ __forceinline__ void lda4(uint32_t* r, uint32_t addr) {
    asm volatile("ldmatrix.sync.aligned.m8n8.x4.shared.b16 {%0,%1,%2,%3}, [%4];"
        : "=r"(r[0]), "=r"(r[1]), "=r"(r[2]), "=r"(r[3]) : "r"(addr));
}
__device__ __forceinline__ void ldb4(uint32_t* r, uint32_t addr) {
    asm volatile("ldmatrix.sync.aligned.m8n8.x4.shared.b16 {%0,%1,%2,%3}, [%4];"
        : "=r"(r[0]), "=r"(r[1]), "=r"(r[2]), "=r"(r[3]) : "r"(addr));
}
__device__ __forceinline__ void mma16816(float* c, const uint32_t* a, const uint32_t* b) {
    asm volatile("mma.sync.aligned.m16n8k16.row.col.f32.bf16.bf16.f32 "
        "{%0,%1,%2,%3}, {%4,%5,%6,%7}, {%8,%9}, {%0,%1,%2,%3};"
        : "+f"(c[0]), "+f"(c[1]), "+f"(c[2]), "+f"(c[3])
        : "r"(a[0]), "r"(a[1]), "r"(a[2]), "r"(a[3]), "r"(b[0]), "r"(b[1]));
}
__device__ __forceinline__ void cp16(uint32_t d, const void* s) {
    asm volatile("cp.async.ca.shared.global [%0], [%1], 16;" :: "r"(d), "l"(s));
}
#define CP_COMMIT() asm volatile("cp.async.commit_group;" ::: "memory")
#define CP_WAIT0()  asm volatile("cp.async.wait_group 0;"  ::: "memory")

// smem layout (round-10 proven): A/B rows 144B; K2 tail reuses [0..34816) for v
// (pitch 68 f32) and O_BUF for mW^T (pitch 68 f32).
enum { O_AHI = 0,                       // H hi : 128 x 144 = 18432
       O_ALO = 18432,                   // H lo : 128 x 144
       O_BUF = 36864,                   // 2 x (Bt hi 9216 + Bt lo 9216) = 36864
       O_B2  = 73728,                   // full b2: 1024 f32 = 4096
       SMEM_SZ = 77824 };

// ============================================================================
// prep: W2 -> bf16 hi/lo, ldmatrix tile layout [col][m2]. 32 blocks, ~5us.
// ============================================================================
__global__ __launch_bounds__(256)
void prep_kernel(const float* __restrict__ W2a, const float* __restrict__ W2b)
{
    const int b = blockIdx.x;              // 0..31
    const int k = b >> 4, t = b & 15;
    const int c = t >> 2, g = t & 3;
    const float* W2 = k ? W2b : W2a;
    const int tid = threadIdx.x;
    #pragma unroll
    for (int it = 0; it < 8; it++) {
        int p = tid + it * 256;            // 2048
        int col = p & 63, m2 = p >> 6;
        float w0 = W2[(size_t)(2 * m2)     * 1024 + c * 256 + g * 64 + col];
        float w1 = W2[(size_t)(2 * m2 + 1) * 1024 + c * 256 + g * 64 + col];
        uint32_t hi, lo;
        split_pack(w0, w1, hi, lo);
        g_Bhi[k][t][col * 32 + m2] = hi;
        g_Blo[k][t][col * 32 + m2] = lo;
    }
}

// ============================================================================
// CSR build: hist -> 2-level exclusive scan -> slot fill
// ============================================================================
__global__ __launch_bounds__(256)
void zero_hist_kernel(int n)
{
    int i = blockIdx.x * 256 + threadIdx.x;
    if (i < n) g_hist[i] = 0;
}

__global__ __launch_bounds__(256)
void hist_kernel(const int* __restrict__ ei, int e)
{
    int i = blockIdx.x * 256 + threadIdx.x;
    if (i < e) atomicAdd(&g_hist[ei[i]], 1);
}

__global__ __launch_bounds__(256)
void scan1_kernel(int n)           // per-block sums of g_hist
{
    __shared__ int sd[256];
    int i = blockIdx.x * 256 + threadIdx.x;
    sd[threadIdx.x] = (i < n) ? g_hist[i] : 0;
    __syncthreads();
    for (int s = 128; s > 0; s >>= 1) {
        if (threadIdx.x < s) sd[threadIdx.x] += sd[threadIdx.x + s];
        __syncthreads();
    }
    if (threadIdx.x == 0) g_bsum[blockIdx.x] = sd[0];
}

__global__ __launch_bounds__(512)
void scan2_kernel(int nb, int n, int e)   // exclusive scan of block sums (nb<=512)
{
    __shared__ int sd[512];
    int t = threadIdx.x;
    sd[t] = (t < nb) ? g_bsum[t] : 0;
    __syncthreads();
    for (int off = 1; off < 512; off <<= 1) {
        int v = sd[t];
        int add = (t >= off) ? sd[t - off] : 0;
        __syncthreads();
        sd[t] = v + add;
        __syncthreads();
    }
    if (t < nb) g_bsum[t] = (t == 0) ? 0 : sd[t - 1];
    if (t == 0) g_rowptr[n] = e;
}

__global__ __launch_bounds__(256)
void scan3_kernel(int n)           // block-local exclusive scan + base -> rowptr/pos
{
    __shared__ int sd[256];
    int i = blockIdx.x * 256 + threadIdx.x, t = threadIdx.x;
    sd[t] = (i < n) ? g_hist[i] : 0;
    __syncthreads();
    for (int off = 1; off < 256; off <<= 1) {
        int v = sd[t];
        int add = (t >= off) ? sd[t - off] : 0;
        __syncthreads();
        sd[t] = v + add;
        __syncthreads();
    }
    if (i < n) {
        int r = g_bsum[blockIdx.x] + ((t == 0) ? 0 : sd[t - 1]);
        g_rowptr[i] = r;
        g_pos[i] = r;
    }
}

__global__ __launch_bounds__(256)
void fill_kernel(const int* __restrict__ ei, int e)
{
    int i = blockIdx.x * 256 + threadIdx.x;
    if (i < e) {
        int dst = ei[i];
        int src = ei[e + i];
        int p = atomicAdd(&g_pos[dst], 1);
        g_eidx[p] = src;
    }
}

// ============================================================================
// gather: 1 warp per node; lanes own 2 features; 2-way unrolled load chains.
// Writes per-node sums to g_acc and degree to g_cnt (no feature atomics).
// ============================================================================
__global__ __launch_bounds__(256)
void gather_kernel(int n)
{
    int w = (blockIdx.x * 256 + threadIdx.x) >> 5;
    int lane = threadIdx.x & 31;
    if (w >= n) return;
    int beg = g_rowptr[w], end = g_rowptr[w + 1];
    float2 a0 = make_float2(0.f, 0.f), a1 = make_float2(0.f, 0.f);
    int j = beg;
    for (; j + 1 < end; j += 2) {
        int s0 = g_eidx[j], s1 = g_eidx[j + 1];
        float2 v0 = *(const float2*)&g_kyv[(size_t)s0 * 64 + lane * 2];
        float2 v1 = *(const float2*)&g_kyv[(size_t)s1 * 64 + lane * 2];
        a0.x += v0.x; a0.y += v0.y;
        a1.x += v1.x; a1.y += v1.y;
    }
    if (j < end) {
        int s = g_eidx[j];
        float2 v = *(const float2*)&g_kyv[(size_t)s * 64 + lane * 2];
        a0.x += v.x; a0.y += v.y;
    }
    *(float2*)&g_acc[(size_t)w * 64 + lane * 2] = make_float2(a0.x + a1.x, a0.y + a1.y);
    if (lane == 0) g_cnt[w] = (float)(end - beg);
}

// ============================================================================
// Fused node kernel (round-10 proven structure, unchanged except the g_acc
// zeroing removal — CSR gather overwrites it).  A hi/lo frags in registers;
// B double-buffered via cp.async; ct tiles in two halves (acc = 16 regs).
// K1 -> g_kyv.  K2: v -> dead A smem region, mix Linear tail.
// ============================================================================
template<int IS_K2>
__global__ __launch_bounds__(256, 2)
void node_kernel(const float* __restrict__ xin, const float* __restrict__ ea,
                 const float* __restrict__ W1, const float* __restrict__ b1,
                 const float* __restrict__ b2,
                 const float* __restrict__ mW, const float* __restrict__ mb,
                 float* __restrict__ out, int n)
{
    extern __shared__ __align__(16) char sm[];
    const uint32_t smb = smem_u32(sm);
    const int tid = threadIdx.x, wid = tid >> 5, lane = tid & 31;
    const int nb = blockIdx.x * TILE;

    // ---- stage A: h = relu(ea@W1+b1) hi/lo bf16, [node][m], row 144B ----
    {
        const int node = tid >> 1, mh = tid & 1;
        const bool ok = (nb + node) < n;
        float e0 = 0.f, e1 = 0.f, e2 = 0.f;
        if (ok) { const float* e = ea + (size_t)(nb + node) * 3; e0 = e[0]; e1 = e[1]; e2 = e[2]; }
        #pragma unroll
        for (int mm = 0; mm < 16; mm++) {
            int m = mh * 32 + mm * 2;
            float h0 = 0.f, h1 = 0.f;
            if (ok) {
                h0 = fmaxf(fmaf(e2, W1[128 + m],     fmaf(e1, W1[64 + m],     fmaf(e0, W1[m],     b1[m]))),     0.f);
                h1 = fmaxf(fmaf(e2, W1[128 + m + 1], fmaf(e1, W1[64 + m + 1], fmaf(e0, W1[m + 1], b1[m + 1]))), 0.f);
            }
            uint32_t hiw, low;
            split_pack(h0, h1, hiw, low);
            uint32_t off = (uint32_t)(node * 144 + m * 2);
            *(uint32_t*)(sm + O_AHI + off) = hiw;
            *(uint32_t*)(sm + O_ALO + off) = low;
        }
    }
    // ---- stage full b2 (1024 f32) once ----
    ((float4*)(sm + O_B2))[tid] = ((const float4*)b2)[tid];
    __syncthreads();                               // A + b2 staged

    // ---- load A fragments ONCE (A smem region dead afterwards) ----
    const uint32_t aRow = (uint32_t)((wid * 16 + (lane & 15)) * 144 + ((lane >> 4) * 16));
    uint32_t ah[4][4], al[4][4];
    #pragma unroll
    for (int ks = 0; ks < 4; ks++) {
        lda4(ah[ks], smb + O_AHI + aRow + ks * 32);
        lda4(al[ks], smb + O_ALO + aRow + ks * 32);
    }

    // x4 B addressing: lanes 16-31 take the next ct tile (+8 rows = +1152B)
    const uint32_t bRow4 = (uint32_t)((lane & 7) * 144 + (((lane >> 3) & 1) * 16)
                                      + ((lane >> 4) * 1152));
    const int r0   = wid * 16 + (lane >> 2);       // C frag rows r0, r0+8
    const int colq = 2 * (lane & 3);

    const int row0 = nb + r0, row1 = nb + r0 + 8;
    const bool v0 = row0 < n, v1 = row1 < n;
    const float* src = IS_K2 ? g_acc : xin;
    float inv0 = 1.f, inv1 = 1.f;
    if (IS_K2) {
        if (v0) inv0 = 1.0f / fmaxf(g_cnt[row0], 1.0f);
        if (v1) inv1 = 1.0f / fmaxf(g_cnt[row1], 1.0f);
    }

    // per-thread cp.async slots (same tile mapping as prep layout)
    const uint32_t st_off0 = (uint32_t)((tid >> 3) * 144 + (tid & 7) * 16);
    const uint32_t st_off1 = (uint32_t)(((tid + 256) >> 3) * 144 + (tid & 7) * 16);

    // ---- prologue: stage tile q=0 into buf 0 ----
    {
        const char* sH = (const char*)g_Bhi[IS_K2][0];
        const char* sL = (const char*)g_Blo[IS_K2][0];
        uint32_t dH = smb + O_BUF;
        cp16(dH + st_off0,        sH + (size_t)tid * 16);
        cp16(dH + 9216 + st_off0, sL + (size_t)tid * 16);
        cp16(dH + st_off1,        sH + (size_t)(tid + 256) * 16);
        cp16(dH + 9216 + st_off1, sL + (size_t)(tid + 256) * 16);
        CP_COMMIT();
    }

    const float* b2s = (const float*)(sm + O_B2);

    for (int c = 0; c < 4; c++) {
        float y[8] = {0.f, 0.f, 0.f, 0.f, 0.f, 0.f, 0.f, 0.f};

        for (int gg = 0; gg < 4; gg++) {
            const int q = c * 4 + gg;
            CP_WAIT0();
            __syncthreads();                       // buf q ready; buf q+1 free
            if (q < 15) {                          // async-stage next tile
                const char* sH = (const char*)g_Bhi[IS_K2][q + 1];
                const char* sL = (const char*)g_Blo[IS_K2][q + 1];
                uint32_t dH = smb + O_BUF + ((q + 1) & 1) * 18432;
                cp16(dH + st_off0,        sH + (size_t)tid * 16);
                cp16(dH + 9216 + st_off0, sL + (size_t)tid * 16);
                cp16(dH + st_off1,        sH + (size_t)(tid + 256) * 16);
                cp16(dH + 9216 + st_off1, sL + (size_t)(tid + 256) * 16);
                CP_COMMIT();
            }

            // x for phase B (load early; read-only data)
            float4 x0 = make_float4(0.f, 0.f, 0.f, 0.f), x1 = x0;
            if (v0) x0 = *(const float4*)&src[(size_t)row0 * 64 + c * 16 + gg * 4];
            if (v1) x1 = *(const float4*)&src[(size_t)row1 * 64 + c * 16 + gg * 4];
            float xk0a[4] = {x0.x, x0.y, x0.z, x0.w};
            float xk1a[4] = {x1.x, x1.y, x1.z, x1.w};

            const uint32_t bufb = smb + O_BUF + (uint32_t)((q & 1) * 18432);

            // ---- HMMA in two ct-halves (acc = 16 regs each) ----
            #pragma unroll
            for (int h = 0; h < 2; h++) {
                float acc[4][4];
                #pragma unroll
                for (int l = 0; l < 4; l++)
                    #pragma unroll
                    for (int p = 0; p < 4; p++) acc[l][p] = 0.f;
                #pragma unroll
                for (int ks = 0; ks < 4; ks++) {
                    #pragma unroll
                    for (int c2 = 0; c2 < 2; c2++) {
                        uint32_t bq[4];
                        ldb4(bq, bufb + (uint32_t)((h * 4 + c2 * 2) * 1152) + bRow4 + ks * 32);
                        mma16816(acc[c2 * 2],     ah[ks], bq);
                        mma16816(acc[c2 * 2 + 1], ah[ks], bq + 2);
                        mma16816(acc[c2 * 2],     al[ks], bq);
                        mma16816(acc[c2 * 2 + 1], al[ks], bq + 2);
                    }
                    #pragma unroll
                    for (int c2 = 0; c2 < 2; c2++) {
                        uint32_t bq[4];
                        ldb4(bq, bufb + 9216u + (uint32_t)((h * 4 + c2 * 2) * 1152) + bRow4 + ks * 32);
                        mma16816(acc[c2 * 2],     ah[ks], bq);
                        mma16816(acc[c2 * 2 + 1], ah[ks], bq + 2);
                    }
                }
                // ---- phase B for this half: ct = h*4+l ----
                #pragma unroll
                for (int l = 0; l < 4; l++) {
                    const int ct = h * 4 + l;
                    const int kl = ct >> 1;
                    const int jb = (ct & 1) * 2;
                    float2 bb = *(const float2*)&b2s[c * 256 + gg * 64 + ct * 8 + colq];
                    y[jb]         = fmaf(xk0a[kl], acc[l][0] + bb.x, y[jb]);
                    y[jb + 1]     = fmaf(xk0a[kl], acc[l][1] + bb.y, y[jb + 1]);
                    y[4 + jb]     = fmaf(xk1a[kl], acc[l][2] + bb.x, y[4 + jb]);
                    y[4 + jb + 1] = fmaf(xk1a[kl], acc[l][3] + bb.y, y[4 + jb + 1]);
                }
            }
        }

        if (!IS_K2) {
            if (v0) {
                *(float2*)&g_kyv[(size_t)row0 * 64 + c * 16 + colq]     = make_float2(y[0], y[1]);
                *(float2*)&g_kyv[(size_t)row0 * 64 + c * 16 + 8 + colq] = make_float2(y[2], y[3]);
            }
            if (v1) {
                *(float2*)&g_kyv[(size_t)row1 * 64 + c * 16 + colq]     = make_float2(y[4], y[5]);
                *(float2*)&g_kyv[(size_t)row1 * 64 + c * 16 + 8 + colq] = make_float2(y[6], y[7]);
            }
        } else {
            // v -> dead A smem region, pitch 68 floats (272B/row), mean folded
            char* vr0 = sm + r0 * 272 + (c * 16 + colq) * 4;
            char* vr1 = sm + (r0 + 8) * 272 + (c * 16 + colq) * 4;
            *(float2*)vr0        = make_float2(y[0] * inv0, y[1] * inv0);
            *(float2*)(vr0 + 32) = make_float2(y[2] * inv0, y[3] * inv0);
            *(float2*)vr1        = make_float2(y[4] * inv1, y[5] * inv1);
            *(float2*)(vr1 + 32) = make_float2(y[6] * inv1, y[7] * inv1);
        }
    }

    // ---- K2 tail: out = v @ mW^T + mb.  v in smem [0..34816), mW^T -> O_BUF.
    if (IS_K2) {
        __syncthreads();                           // v writes + B reads done
        #pragma unroll
        for (int it = 0; it < 16; it++) {
            int p = tid + it * 256;                // 4096
            int j = p >> 6, i = p & 63;
            *(float*)(sm + O_BUF + (j * 68 + i) * 4) = mW[(size_t)i * 64 + j];
        }
        __syncthreads();
        const int node_b = tid >> 1, jh = tid & 1;
        if (nb + node_b < n) {
            float a[32];
            #pragma unroll
            for (int p = 0; p < 8; p++) {
                float4 m4 = ((const float4*)mb)[jh * 8 + p];
                a[p*4] = m4.x; a[p*4+1] = m4.y; a[p*4+2] = m4.z; a[p*4+3] = m4.w;
            }
            #pragma unroll 4
            for (int j = 0; j < 64; j++) {
                float vj = *(const float*)(sm + (node_b * 68 + j) * 4);
                #pragma unroll
                for (int p = 0; p < 8; p++) {
                    float4 w = *(const float4*)(sm + O_BUF + (j * 68 + jh * 32 + p * 4) * 4);
                    a[p*4]   = fmaf(vj, w.x, a[p*4]);
                    a[p*4+1] = fmaf(vj, w.y, a[p*4+1]);
                    a[p*4+2] = fmaf(vj, w.z, a[p*4+2]);
                    a[p*4+3] = fmaf(vj, w.w, a[p*4+3]);
                }
            }
            float* dst = &out[(size_t)(nb + node_b) * 64 + jh * 32];
            #pragma unroll
            for (int p = 0; p < 8; p++)
                ((float4*)dst)[p] = make_float4(a[p*4], a[p*4+1], a[p*4+2], a[p*4+3]);
        }
    }
}

// ============================================================================
extern "C" void kernel_launch(void* const* d_in, const int* in_sizes, int n_in,
                              void* d_out, int out_size)
{
    const float* x    = (const float*)d_in[0];
    const float* ea   = (const float*)d_in[1];
    const int*   ei   = (const int*)  d_in[2];
    const float* k1W1 = (const float*)d_in[3];
    const float* k1b1 = (const float*)d_in[4];
    const float* k1W2 = (const float*)d_in[5];
    const float* k1b2 = (const float*)d_in[6];
    const float* k2W1 = (const float*)d_in[7];
    const float* k2b1 = (const float*)d_in[8];
    const float* k2W2 = (const float*)d_in[9];
    const float* k2b2 = (const float*)d_in[10];
    const float* mW   = (const float*)d_in[11];
    const float* mb   = (const float*)d_in[12];
    float* out = (float*)d_out;

    const int n = in_sizes[0] / 64;        // 100000
    const int e = in_sizes[2] / 2;         // 3200000

    cudaFuncSetAttribute(node_kernel<0>, cudaFuncAttributeMaxDynamicSharedMemorySize, SMEM_SZ);
    cudaFuncSetAttribute(node_kernel<1>, cudaFuncAttributeMaxDynamicSharedMemorySize, SMEM_SZ);

    const int node_blocks = (n + TILE - 1) / TILE;
    const int nblk  = (n + 255) / 256;     // 391 for n=100000
    const int eblk  = (e + 255) / 256;
    const int gblk  = (n * 32 + 255) / 256;

    prep_kernel<<<32, 256>>>(k1W2, k2W2);
    // CSR build (independent of K1; deterministic work every call)
    zero_hist_kernel<<<nblk, 256>>>(n);
    hist_kernel<<<eblk, 256>>>(ei, e);
    scan1_kernel<<<nblk, 256>>>(n);
    scan2_kernel<<<1, 512>>>(nblk, n, e);
    scan3_kernel<<<nblk, 256>>>(n);
    fill_kernel<<<eblk, 256>>>(ei, e);
    // K1: ky_v
    node_kernel<0><<<node_blocks, 256, SMEM_SZ>>>(x, ea, k1W1, k1b1, k1b2,
                                                  nullptr, nullptr, nullptr, n);
    // atomic-free gather-reduce (sums + degrees)
    gather_kernel<<<gblk, 256>>>(n);
    // K2 + mix
    node_kernel<1><<<node_blocks, 256, SMEM_SZ>>>(nullptr, ea, k2W1, k2b1, k2b2,
                                                  mW, mb, out, n);
}

// round 13
// speedup vs baseline: 1.3287x; 1.2441x over previous
#include <cuda_runtime.h>
#include <cuda_bf16.h>
#include <cstdint>

#define NN    100000
#define EE    3200000
#define TILE  128
#define FILLB 256

// ---- scratch (allocation-free rule: __device__ globals) ----
__device__ float g_kyv[NN * 64];            // K1 output ky_v
__device__ float g_acc[NN * 64];            // per-node message sums
__device__ float g_cnt[NN];                 // per-node degree (float)
__device__ uint32_t g_Bhi[2][16][2048];     // prepacked W2 hi bf16 pairs [kid][c*4+g][col*32+m2]
__device__ uint32_t g_Blo[2][16][2048];     // prepacked W2 lo
__device__ uint32_t g_Mhi[2048];            // prepacked mW^T hi (B-tile layout)
__device__ uint32_t g_Mlo[2048];            // prepacked mW^T lo
// CSR scratch
__device__ int g_hist[NN];
__device__ int g_rowptr[NN + 1];
__device__ int g_pos[NN];
__device__ int g_eidx[EE];
__device__ int g_bsum[512];

// ============================================================================
// helpers
// ============================================================================
__device__ __forceinline__ uint32_t smem_u32(const void* p) {
    uint32_t a;
    asm("{ .reg .u64 t; cvta.to.shared.u64 t, %1; cvt.u32.u64 %0, t; }" : "=r"(a) : "l"(p));
    return a;
}
__device__ __forceinline__ void split_pack(float v0, float v1, uint32_t& hiw, uint32_t& low) {
    __nv_bfloat16 h0 = __float2bfloat16(v0), h1 = __float2bfloat16(v1);
    __nv_bfloat16 l0 = __float2bfloat16(v0 - __bfloat162float(h0));
    __nv_bfloat16 l1 = __float2bfloat16(v1 - __bfloat162float(h1));
    hiw = (uint32_t)__bfloat16_as_ushort(h0) | ((uint32_t)__bfloat16_as_ushort(h1) << 16);
    low = (uint32_t)__bfloat16_as_ushort(l0) | ((uint32_t)__bfloat16_as_ushort(l1) << 16);
}
__device__ __forceinline__ void lda4(uint32_t* r, uint32_t addr) {
    asm volatile("ldmatrix.sync.aligned.m8n8.x4.shared.b16 {%0,%1,%2,%3}, [%4];"
        : "=r"(r[0]), "=r"(r[1]), "=r"(r[2]), "=r"(r[3]) : "r"(addr));
}
__device__ __forceinline__ void ldb4(uint32_t* r, uint32_t addr) {
    asm volatile("ldmatrix.sync.aligned.m8n8.x4.shared.b16 {%0,%1,%2,%3}, [%4];"
        : "=r"(r[0]), "=r"(r[1]), "=r"(r[2]), "=r"(r[3]) : "r"(addr));
}
__device__ __forceinline__ void mma16816(float* c, const uint32_t* a, const uint32_t* b) {
    asm volatile("mma.sync.aligned.m16n8k16.row.col.f32.bf16.bf16.f32 "
        "{%0,%1,%2,%3}, {%4,%5,%6,%7}, {%8,%9}, {%0,%1,%2,%3};"
        : "+f"(c[0]), "+f"(c[1]), "+f"(c[2]), "+f"(c[3])
        : "r"(a[0]), "r"(a[1]), "r"(a[2]), "r"(a[3]), "r"(b[0]), "r"(b[1]));
}
__device__ __forceinline__ void cp16(uint32_t d, const void* s) {
    asm volatile("cp.async.ca.shared.global [%0], [%1], 16;" :: "r"(d), "l"(s));
}
#define CP_COMMIT() asm volatile("cp.async.commit_group;" ::: "memory")
#define CP_WAIT0()  asm volatile("cp.async.wait_group 0;"  ::: "memory")

// smem layout (round-10/12 proven). A/B rows 144B. K2 tail stages v (bf16 hi/lo,
// stage-A layout) back into the dead A regions and mW^T into O_BUF buf 0.
enum { O_AHI = 0,                       // H hi : 128 x 144 = 18432
       O_ALO = 18432,                   // H lo : 128 x 144
       O_BUF = 36864,                   // 2 x (Bt hi 9216 + Bt lo 9216) = 36864
       O_B2  = 73728,                   // full b2: 1024 f32 = 4096
       SMEM_SZ = 77824 };

// ============================================================================
// prep: W2 -> bf16 hi/lo B-tiles (blocks 0..31); block 32: mW^T mix tile.
// ============================================================================
__global__ __launch_bounds__(256)
void prep_kernel(const float* __restrict__ W2a, const float* __restrict__ W2b,
                 const float* __restrict__ mW)
{
    const int b = blockIdx.x;              // 0..32
    const int tid = threadIdx.x;
    if (b == 32) {                         // mix tile: B[col][m2] = (mW[col][2m2], mW[col][2m2+1])
        #pragma unroll
        for (int it = 0; it < 8; it++) {
            int p = tid + it * 256;        // 2048, p = col*32 + m2
            int col = p >> 5, m2 = p & 31;
            float w0 = mW[(size_t)col * 64 + 2 * m2];
            float w1 = mW[(size_t)col * 64 + 2 * m2 + 1];
            uint32_t hi, lo;
            split_pack(w0, w1, hi, lo);
            g_Mhi[p] = hi;
            g_Mlo[p] = lo;
        }
        return;
    }
    const int k = b >> 4, t = b & 15;
    const int c = t >> 2, g = t & 3;
    const float* W2 = k ? W2b : W2a;
    #pragma unroll
    for (int it = 0; it < 8; it++) {
        int p = tid + it * 256;            // 2048
        int col = p & 63, m2 = p >> 6;
        float w0 = W2[(size_t)(2 * m2)     * 1024 + c * 256 + g * 64 + col];
        float w1 = W2[(size_t)(2 * m2 + 1) * 1024 + c * 256 + g * 64 + col];
        uint32_t hi, lo;
        split_pack(w0, w1, hi, lo);
        g_Bhi[k][t][col * 32 + m2] = hi;
        g_Blo[k][t][col * 32 + m2] = lo;
    }
}

// ============================================================================
// CSR build: hist -> 2-level exclusive scan (fill is fused into K1's launch)
// ============================================================================
__global__ __launch_bounds__(256)
void zero_hist_kernel(int n)
{
    int i = blockIdx.x * 256 + threadIdx.x;
    if (i < n) g_hist[i] = 0;
}

__global__ __launch_bounds__(256)
void hist_kernel(const int* __restrict__ ei, int e)
{
    int i = blockIdx.x * 256 + threadIdx.x;
    if (i < e) atomicAdd(&g_hist[ei[i]], 1);
}

__global__ __launch_bounds__(256)
void scan1_kernel(int n)           // per-block sums of g_hist
{
    __shared__ int sd[256];
    int i = blockIdx.x * 256 + threadIdx.x;
    sd[threadIdx.x] = (i < n) ? g_hist[i] : 0;
    __syncthreads();
    for (int s = 128; s > 0; s >>= 1) {
        if (threadIdx.x < s) sd[threadIdx.x] += sd[threadIdx.x + s];
        __syncthreads();
    }
    if (threadIdx.x == 0) g_bsum[blockIdx.x] = sd[0];
}

__global__ __launch_bounds__(512)
void scan2_kernel(int nb, int n, int e)   // exclusive scan of block sums (nb<=512)
{
    __shared__ int sd[512];
    int t = threadIdx.x;
    sd[t] = (t < nb) ? g_bsum[t] : 0;
    __syncthreads();
    for (int off = 1; off < 512; off <<= 1) {
        int v = sd[t];
        int add = (t >= off) ? sd[t - off] : 0;
        __syncthreads();
        sd[t] = v + add;
        __syncthreads();
    }
    if (t < nb) g_bsum[t] = (t == 0) ? 0 : sd[t - 1];
    if (t == 0) g_rowptr[n] = e;
}

__global__ __launch_bounds__(256)
void scan3_kernel(int n)           // block-local exclusive scan + base -> rowptr/pos
{
    __shared__ int sd[256];
    int i = blockIdx.x * 256 + threadIdx.x, t = threadIdx.x;
    sd[t] = (i < n) ? g_hist[i] : 0;
    __syncthreads();
    for (int off = 1; off < 256; off <<= 1) {
        int v = sd[t];
        int add = (t >= off) ? sd[t - off] : 0;
        __syncthreads();
        sd[t] = v + add;
        __syncthreads();
    }
    if (i < n) {
        int r = g_bsum[blockIdx.x] + ((t == 0) ? 0 : sd[t - 1]);
        g_rowptr[i] = r;
        g_pos[i] = r;
    }
}

// ============================================================================
// gather: 1 warp per node; half-warp per edge, l16 lanes own float4 (verified
// scatter addressing). Writes sums to g_acc and degree to g_cnt; no atomics.
// ============================================================================
__global__ __launch_bounds__(256)
void gather_kernel(int n)
{
    int w = (blockIdx.x * 256 + threadIdx.x) >> 5;
    int lane = threadIdx.x & 31;
    if (w >= n) return;
    int beg = g_rowptr[w], end = g_rowptr[w + 1];
    int half = lane >> 4, l16 = lane & 15;
    float4 a = make_float4(0.f, 0.f, 0.f, 0.f);
    for (int j = beg + half; j < end; j += 2) {
        int s = g_eidx[j];
        float4 v = *(const float4*)&g_kyv[(size_t)s * 64 + l16 * 4];
        a.x += v.x; a.y += v.y; a.z += v.z; a.w += v.w;
    }
    // combine halves (lanes 0-15 += lanes 16-31)
    a.x += __shfl_down_sync(0xFFFFFFFFu, a.x, 16);
    a.y += __shfl_down_sync(0xFFFFFFFFu, a.y, 16);
    a.z += __shfl_down_sync(0xFFFFFFFFu, a.z, 16);
    a.w += __shfl_down_sync(0xFFFFFFFFu, a.w, 16);
    if (half == 0)
        *(float4*)&g_acc[(size_t)w * 64 + l16 * 4] = a;
    if (lane == 0) g_cnt[w] = (float)(end - beg);
}

// ============================================================================
// Fused node kernel (round-12 proven mainloop).  K1's launch carries FILLB
// extra leading blocks that do the CSR slot-fill (grid-stride), overlapping
// the heavy node waves.  K2 tail: v -> bf16 hi/lo in dead A region (stage-A
// layout), mW^T tile -> O_BUF, one verified 3-pass MMA group -> out (+mb).
// ============================================================================
template<int IS_K2>
__global__ __launch_bounds__(256, 2)
void node_kernel(const float* __restrict__ xin, const float* __restrict__ ea,
                 const float* __restrict__ W1, const float* __restrict__ b1,
                 const float* __restrict__ b2,
                 const float* __restrict__ mb,
                 const int* __restrict__ ei, int e,
                 float* __restrict__ out, int n)
{
    // ---- K1-only: CSR fill in leading blocks (depends on scan3, done) ----
    if (!IS_K2 && blockIdx.x < FILLB) {
        for (int i = blockIdx.x * 256 + threadIdx.x; i < e; i += FILLB * 256) {
            int dst = ei[i];
            int src = ei[e + i];
            int p = atomicAdd(&g_pos[dst], 1);
            g_eidx[p] = src;
        }
        return;
    }

    extern __shared__ __align__(16) char sm[];
    const uint32_t smb = smem_u32(sm);
    const int tid = threadIdx.x, wid = tid >> 5, lane = tid & 31;
    const int nb = (IS_K2 ? blockIdx.x : (blockIdx.x - FILLB)) * TILE;

    // ---- stage A: h = relu(ea@W1+b1) hi/lo bf16, [node][m], row 144B ----
    {
        const int node = tid >> 1, mh = tid & 1;
        const bool ok = (nb + node) < n;
        float e0 = 0.f, e1 = 0.f, e2 = 0.f;
        if (ok) { const float* ep = ea + (size_t)(nb + node) * 3; e0 = ep[0]; e1 = ep[1]; e2 = ep[2]; }
        #pragma unroll
        for (int mm = 0; mm < 16; mm++) {
            int m = mh * 32 + mm * 2;
            float h0 = 0.f, h1 = 0.f;
            if (ok) {
                h0 = fmaxf(fmaf(e2, W1[128 + m],     fmaf(e1, W1[64 + m],     fmaf(e0, W1[m],     b1[m]))),     0.f);
                h1 = fmaxf(fmaf(e2, W1[128 + m + 1], fmaf(e1, W1[64 + m + 1], fmaf(e0, W1[m + 1], b1[m + 1]))), 0.f);
            }
            uint32_t hiw, low;
            split_pack(h0, h1, hiw, low);
            uint32_t off = (uint32_t)(node * 144 + m * 2);
            *(uint32_t*)(sm + O_AHI + off) = hiw;
            *(uint32_t*)(sm + O_ALO + off) = low;
        }
    }
    // ---- stage full b2 (1024 f32) once ----
    ((float4*)(sm + O_B2))[tid] = ((const float4*)b2)[tid];
    __syncthreads();                               // A + b2 staged

    // ---- load A fragments ONCE (A smem region dead afterwards) ----
    const uint32_t aRow = (uint32_t)((wid * 16 + (lane & 15)) * 144 + ((lane >> 4) * 16));
    uint32_t ah[4][4], al[4][4];
    #pragma unroll
    for (int ks = 0; ks < 4; ks++) {
        lda4(ah[ks], smb + O_AHI + aRow + ks * 32);
        lda4(al[ks], smb + O_ALO + aRow + ks * 32);
    }

    // x4 B addressing: lanes 16-31 take the next ct tile (+8 rows = +1152B)
    const uint32_t bRow4 = (uint32_t)((lane & 7) * 144 + (((lane >> 3) & 1) * 16)
                                      + ((lane >> 4) * 1152));
    const int r0   = wid * 16 + (lane >> 2);       // C frag rows r0, r0+8
    const int colq = 2 * (lane & 3);

    const int row0 = nb + r0, row1 = nb + r0 + 8;
    const bool v0 = row0 < n, v1 = row1 < n;
    const float* src = IS_K2 ? g_acc : xin;
    float inv0 = 1.f, inv1 = 1.f;
    if (IS_K2) {
        if (v0) inv0 = 1.0f / fmaxf(g_cnt[row0], 1.0f);
        if (v1) inv1 = 1.0f / fmaxf(g_cnt[row1], 1.0f);
    }

    // per-thread cp.async slots (same tile mapping as prep layout)
    const uint32_t st_off0 = (uint32_t)((tid >> 3) * 144 + (tid & 7) * 16);
    const uint32_t st_off1 = (uint32_t)(((tid + 256) >> 3) * 144 + (tid & 7) * 16);

    // ---- prologue: stage tile q=0 into buf 0 ----
    {
        const char* sH = (const char*)g_Bhi[IS_K2][0];
        const char* sL = (const char*)g_Blo[IS_K2][0];
        uint32_t dH = smb + O_BUF;
        cp16(dH + st_off0,        sH + (size_t)tid * 16);
        cp16(dH + 9216 + st_off0, sL + (size_t)tid * 16);
        cp16(dH + st_off1,        sH + (size_t)(tid + 256) * 16);
        cp16(dH + 9216 + st_off1, sL + (size_t)(tid + 256) * 16);
        CP_COMMIT();
    }

    const float* b2s = (const float*)(sm + O_B2);

    for (int c = 0; c < 4; c++) {
        float y[8] = {0.f, 0.f, 0.f, 0.f, 0.f, 0.f, 0.f, 0.f};

        for (int gg = 0; gg < 4; gg++) {
            const int q = c * 4 + gg;
            CP_WAIT0();
            __syncthreads();                       // buf q ready; buf q+1 free
            if (q < 15) {                          // async-stage next tile
                const char* sH = (const char*)g_Bhi[IS_K2][q + 1];
                const char* sL = (const char*)g_Blo[IS_K2][q + 1];
                uint32_t dH = smb + O_BUF + ((q + 1) & 1) * 18432;
                cp16(dH + st_off0,        sH + (size_t)tid * 16);
                cp16(dH + 9216 + st_off0, sL + (size_t)tid * 16);
                cp16(dH + st_off1,        sH + (size_t)(tid + 256) * 16);
                cp16(dH + 9216 + st_off1, sL + (size_t)(tid + 256) * 16);
                CP_COMMIT();
            }

            // x for phase B (load early; read-only data)
            float4 x0 = make_float4(0.f, 0.f, 0.f, 0.f), x1 = x0;
            if (v0) x0 = *(const float4*)&src[(size_t)row0 * 64 + c * 16 + gg * 4];
            if (v1) x1 = *(const float4*)&src[(size_t)row1 * 64 + c * 16 + gg * 4];
            float xk0a[4] = {x0.x, x0.y, x0.z, x0.w};
            float xk1a[4] = {x1.x, x1.y, x1.z, x1.w};

            const uint32_t bufb = smb + O_BUF + (uint32_t)((q & 1) * 18432);

            // ---- HMMA in two ct-halves (acc = 16 regs each) ----
            #pragma unroll
            for (int h = 0; h < 2; h++) {
                float acc[4][4];
                #pragma unroll
                for (int l = 0; l < 4; l++)
                    #pragma unroll
                    for (int p = 0; p < 4; p++) acc[l][p] = 0.f;
                #pragma unroll
                for (int ks = 0; ks < 4; ks++) {
                    #pragma unroll
                    for (int c2 = 0; c2 < 2; c2++) {
                        uint32_t bq[4];
                        ldb4(bq, bufb + (uint32_t)((h * 4 + c2 * 2) * 1152) + bRow4 + ks * 32);
                        mma16816(acc[c2 * 2],     ah[ks], bq);
                        mma16816(acc[c2 * 2 + 1], ah[ks], bq + 2);
                        mma16816(acc[c2 * 2],     al[ks], bq);
                        mma16816(acc[c2 * 2 + 1], al[ks], bq + 2);
                    }
                    #pragma unroll
                    for (int c2 = 0; c2 < 2; c2++) {
                        uint32_t bq[4];
                        ldb4(bq, bufb + 9216u + (uint32_t)((h * 4 + c2 * 2) * 1152) + bRow4 + ks * 32);
                        mma16816(acc[c2 * 2],     ah[ks], bq);
                        mma16816(acc[c2 * 2 + 1], ah[ks], bq + 2);
                    }
                }
                // ---- phase B for this half: ct = h*4+l ----
                #pragma unroll
                for (int l = 0; l < 4; l++) {
                    const int ct = h * 4 + l;
                    const int kl = ct >> 1;
                    const int jb = (ct & 1) * 2;
                    float2 bb = *(const float2*)&b2s[c * 256 + gg * 64 + ct * 8 + colq];
                    y[jb]         = fmaf(xk0a[kl], acc[l][0] + bb.x, y[jb]);
                    y[jb + 1]     = fmaf(xk0a[kl], acc[l][1] + bb.y, y[jb + 1]);
                    y[4 + jb]     = fmaf(xk1a[kl], acc[l][2] + bb.x, y[4 + jb]);
                    y[4 + jb + 1] = fmaf(xk1a[kl], acc[l][3] + bb.y, y[4 + jb + 1]);
                }
            }
        }

        if (!IS_K2) {
            if (v0) {
                *(float2*)&g_kyv[(size_t)row0 * 64 + c * 16 + colq]     = make_float2(y[0], y[1]);
                *(float2*)&g_kyv[(size_t)row0 * 64 + c * 16 + 8 + colq] = make_float2(y[2], y[3]);
            }
            if (v1) {
                *(float2*)&g_kyv[(size_t)row1 * 64 + c * 16 + colq]     = make_float2(y[4], y[5]);
                *(float2*)&g_kyv[(size_t)row1 * 64 + c * 16 + 8 + colq] = make_float2(y[6], y[7]);
            }
        } else {
            // v (mean folded) -> bf16 hi/lo in dead A regions, stage-A layout:
            // row*144 + col*2, value pairs at even cols (colq even).
            uint32_t hi, lo;
            uint32_t o0 = (uint32_t)(r0 * 144 + (c * 16 + colq) * 2);
            split_pack(y[0] * inv0, y[1] * inv0, hi, lo);
            *(uint32_t*)(sm + O_AHI + o0) = hi;  *(uint32_t*)(sm + O_ALO + o0) = lo;
            uint32_t o1 = (uint32_t)(r0 * 144 + (c * 16 + 8 + colq) * 2);
            split_pack(y[2] * inv0, y[3] * inv0, hi, lo);
            *(uint32_t*)(sm + O_AHI + o1) = hi;  *(uint32_t*)(sm + O_ALO + o1) = lo;
            uint32_t o2 = (uint32_t)((r0 + 8) * 144 + (c * 16 + colq) * 2);
            split_pack(y[4] * inv1, y[5] * inv1, hi, lo);
            *(uint32_t*)(sm + O_AHI + o2) = hi;  *(uint32_t*)(sm + O_ALO + o2) = lo;
            uint32_t o3 = (uint32_t)((r0 + 8) * 144 + (c * 16 + 8 + colq) * 2);
            split_pack(y[6] * inv1, y[7] * inv1, hi, lo);
            *(uint32_t*)(sm + O_AHI + o3) = hi;  *(uint32_t*)(sm + O_ALO + o3) = lo;
        }
    }

    // ---- K2 tail: out = v @ mW^T + mb via ONE verified MMA group ----
    if (IS_K2) {
        __syncthreads();                           // all v bf16 writes visible
        // stage mix B tile into buf 0 (same cp16 mapping as mainloop)
        {
            uint32_t dH = smb + O_BUF;
            cp16(dH + st_off0,        (const char*)g_Mhi + (size_t)tid * 16);
            cp16(dH + 9216 + st_off0, (const char*)g_Mlo + (size_t)tid * 16);
            cp16(dH + st_off1,        (const char*)g_Mhi + (size_t)(tid + 256) * 16);
            cp16(dH + 9216 + st_off1, (const char*)g_Mlo + (size_t)(tid + 256) * 16);
            CP_COMMIT();
            CP_WAIT0();
        }
        __syncthreads();                           // mix B ready
        // reload A frags = v (same addressing as H)
        #pragma unroll
        for (int ks = 0; ks < 4; ks++) {
            lda4(ah[ks], smb + O_AHI + aRow + ks * 32);
            lda4(al[ks], smb + O_ALO + aRow + ks * 32);
        }
        const uint32_t bufb = smb + O_BUF;
        #pragma unroll
        for (int h = 0; h < 2; h++) {
            float acc[4][4];
            #pragma unroll
            for (int l = 0; l < 4; l++)
                #pragma unroll
                for (int p = 0; p < 4; p++) acc[l][p] = 0.f;
            #pragma unroll
            for (int ks = 0; ks < 4; ks++) {
                #pragma unroll
                for (int c2 = 0; c2 < 2; c2++) {
                    uint32_t bq[4];
                    ldb4(bq, bufb + (uint32_t)((h * 4 + c2 * 2) * 1152) + bRow4 + ks * 32);
                    mma16816(acc[c2 * 2],     ah[ks], bq);
                    mma16816(acc[c2 * 2 + 1], ah[ks], bq + 2);
                    mma16816(acc[c2 * 2],     al[ks], bq);
                    mma16816(acc[c2 * 2 + 1], al[ks], bq + 2);
                }
                #pragma unroll
                for (int c2 = 0; c2 < 2; c2++) {
                    uint32_t bq[4];
                    ldb4(bq, bufb + 9216u + (uint32_t)((h * 4 + c2 * 2) * 1152) + bRow4 + ks * 32);
                    mma16816(acc[c2 * 2],     ah[ks], bq);
                    mma16816(acc[c2 * 2 + 1], ah[ks], bq + 2);
                }
            }
            // write C frags (+mb): acc[l][0,1] -> row0 cols ct*8+colq(+1);
            //                      acc[l][2,3] -> row1 (verified mapping)
            #pragma unroll
            for (int l = 0; l < 4; l++) {
                const int ct = h * 4 + l;
                float2 mbv = *(const float2*)&mb[ct * 8 + colq];
                if (v0) *(float2*)&out[(size_t)row0 * 64 + ct * 8 + colq] =
                            make_float2(acc[l][0] + mbv.x, acc[l][1] + mbv.y);
                if (v1) *(float2*)&out[(size_t)row1 * 64 + ct * 8 + colq] =
                            make_float2(acc[l][2] + mbv.x, acc[l][3] + mbv.y);
            }
        }
    }
}

// ============================================================================
extern "C" void kernel_launch(void* const* d_in, const int* in_sizes, int n_in,
                              void* d_out, int out_size)
{
    const float* x    = (const float*)d_in[0];
    const float* ea   = (const float*)d_in[1];
    const int*   ei   = (const int*)  d_in[2];
    const float* k1W1 = (const float*)d_in[3];
    const float* k1b1 = (const float*)d_in[4];
    const float* k1W2 = (const float*)d_in[5];
    const float* k1b2 = (const float*)d_in[6];
    const float* k2W1 = (const float*)d_in[7];
    const float* k2b1 = (const float*)d_in[8];
    const float* k2W2 = (const float*)d_in[9];
    const float* k2b2 = (const float*)d_in[10];
    const float* mW   = (const float*)d_in[11];
    const float* mb   = (const float*)d_in[12];
    float* out = (float*)d_out;

    const int n = in_sizes[0] / 64;        // 100000
    const int e = in_sizes[2] / 2;         // 3200000

    cudaFuncSetAttribute(node_kernel<0>, cudaFuncAttributeMaxDynamicSharedMemorySize, SMEM_SZ);
    cudaFuncSetAttribute(node_kernel<1>, cudaFuncAttributeMaxDynamicSharedMemorySize, SMEM_SZ);

    const int node_blocks = (n + TILE - 1) / TILE;
    const int nblk  = (n + 255) / 256;     // 391 for n=100000
    const int eblk  = (e + 255) / 256;
    const int gblk  = (n * 32 + 255) / 256;

    prep_kernel<<<33, 256>>>(k1W2, k2W2, mW);
    // CSR build (fill is fused into K1's leading blocks)
    zero_hist_kernel<<<nblk, 256>>>(n);
    hist_kernel<<<eblk, 256>>>(ei, e);
    scan1_kernel<<<nblk, 256>>>(n);
    scan2_kernel<<<1, 512>>>(nblk, n, e);
    scan3_kernel<<<nblk, 256>>>(n);
    // K1: ky_v  (+ FILLB leading blocks doing CSR fill, overlapped)
    node_kernel<0><<<node_blocks + FILLB, 256, SMEM_SZ>>>(x, ea, k1W1, k1b1, k1b2,
                                                          nullptr, ei, e, nullptr, n);
    // atomic-free gather-reduce (sums + degrees)
    gather_kernel<<<gblk, 256>>>(n);
    // K2 + HMMA mix tail
    node_kernel<1><<<node_blocks, 256, SMEM_SZ>>>(nullptr, ea, k2W1, k2b1, k2b2,
                                                  mb, nullptr, 0, out, n);
}

// round 14
// speedup vs baseline: 1.3367x; 1.0060x over previous
#include <cuda_runtime.h>
#include <cuda_bf16.h>
#include <cstdint>

#define NN    100000
#define EE    3200000
#define TILE  128
#define FILLB 256

// ---- scratch (allocation-free rule: __device__ globals) ----
__device__ float g_kyv[NN * 64];            // K1 output ky_v
__device__ float g_acc[NN * 64];            // per-node message MEANS (mean folded in gather)
__device__ uint32_t g_Bhi[2][16][2048];     // prepacked W2 hi bf16 pairs [kid][c*4+g][col*32+m2]
__device__ uint32_t g_Blo[2][16][2048];     // prepacked W2 lo
__device__ uint32_t g_Mhi[2048];            // prepacked mW^T hi (B-tile layout)
__device__ uint32_t g_Mlo[2048];            // prepacked mW^T lo
// CSR scratch
__device__ int g_hist[NN];                  // zero-initialized; scan3 re-zeroes each run
__device__ int g_rowptr[NN + 1];
__device__ int g_pos[NN];
__device__ int g_eidx[EE];
__device__ int g_bsum[512];
__device__ int g_done = 0;

// ============================================================================
// helpers
// ============================================================================
__device__ __forceinline__ uint32_t smem_u32(const void* p) {
    uint32_t a;
    asm("{ .reg .u64 t; cvta.to.shared.u64 t, %1; cvt.u32.u64 %0, t; }" : "=r"(a) : "l"(p));
    return a;
}
__device__ __forceinline__ void split_pack(float v0, float v1, uint32_t& hiw, uint32_t& low) {
    __nv_bfloat16 h0 = __float2bfloat16(v0), h1 = __float2bfloat16(v1);
    __nv_bfloat16 l0 = __float2bfloat16(v0 - __bfloat162float(h0));
    __nv_bfloat16 l1 = __float2bfloat16(v1 - __bfloat162float(h1));
    hiw = (uint32_t)__bfloat16_as_ushort(h0) | ((uint32_t)__bfloat16_as_ushort(h1) << 16);
    low = (uint32_t)__bfloat16_as_ushort(l0) | ((uint32_t)__bfloat16_as_ushort(l1) << 16);
}
__device__ __forceinline__ void lda4(uint32_t* r, uint32_t addr) {
    asm volatile("ldmatrix.sync.aligned.m8n8.x4.shared.b16 {%0,%1,%2,%3}, [%4];"
        : "=r"(r[0]), "=r"(r[1]), "=r"(r[2]), "=r"(r[3]) : "r"(addr));
}
__device__ __forceinline__ void ldb4(uint32_t* r, uint32_t addr) {
    asm volatile("ldmatrix.sync.aligned.m8n8.x4.shared.b16 {%0,%1,%2,%3}, [%4];"
        : "=r"(r[0]), "=r"(r[1]), "=r"(r[2]), "=r"(r[3]) : "r"(addr));
}
__device__ __forceinline__ void mma16816(float* c, const uint32_t* a, const uint32_t* b) {
    asm volatile("mma.sync.aligned.m16n8k16.row.col.f32.bf16.bf16.f32 "
        "{%0,%1,%2,%3}, {%4,%5,%6,%7}, {%8,%9}, {%0,%1,%2,%3};"
        : "+f"(c[0]), "+f"(c[1]), "+f"(c[2]), "+f"(c[3])
        : "r"(a[0]), "r"(a[1]), "r"(a[2]), "r"(a[3]), "r"(b[0]), "r"(b[1]));
}
__device__ __forceinline__ void cp16(uint32_t d, const void* s) {
    asm volatile("cp.async.ca.shared.global [%0], [%1], 16;" :: "r"(d), "l"(s));
}
#define CP_COMMIT() asm volatile("cp.async.commit_group;" ::: "memory")
#define CP_WAIT0()  asm volatile("cp.async.wait_group 0;"  ::: "memory")

// smem layout (proven). A/B rows 144B. K2 tail stages v (bf16 hi/lo, stage-A
// layout) back into the dead A regions and mW^T into O_BUF buf 0.
enum { O_AHI = 0,                       // H hi : 128 x 144 = 18432
       O_ALO = 18432,                   // H lo : 128 x 144
       O_BUF = 36864,                   // 2 x (Bt hi 9216 + Bt lo 9216) = 36864
       O_B2  = 73728,                   // full b2: 1024 f32 = 4096
       SMEM_SZ = 77824 };

// ============================================================================
// prep + hist fused: blocks 0..31 -> W2 B-tiles; block 32 -> mix tile;
// blocks 33.. -> edge histogram (g_hist zeroed by previous run's scan3).
// ============================================================================
__global__ __launch_bounds__(256)
void prep_hist_kernel(const float* __restrict__ W2a, const float* __restrict__ W2b,
                      const float* __restrict__ mW,
                      const int* __restrict__ ei, int e)
{
    const int b = blockIdx.x;
    const int tid = threadIdx.x;
    if (b >= 33) {                         // histogram part
        int i = (b - 33) * 256 + tid;
        if (i < e) atomicAdd(&g_hist[ei[i]], 1);
        return;
    }
    if (b == 32) {                         // mix tile: B[col][m2] = (mW[col][2m2], mW[col][2m2+1])
        #pragma unroll
        for (int it = 0; it < 8; it++) {
            int p = tid + it * 256;        // 2048, p = col*32 + m2
            int col = p >> 5, m2 = p & 31;
            float w0 = mW[(size_t)col * 64 + 2 * m2];
            float w1 = mW[(size_t)col * 64 + 2 * m2 + 1];
            uint32_t hi, lo;
            split_pack(w0, w1, hi, lo);
            g_Mhi[p] = hi;
            g_Mlo[p] = lo;
        }
        return;
    }
    const int k = b >> 4, t = b & 15;
    const int c = t >> 2, g = t & 3;
    const float* W2 = k ? W2b : W2a;
    #pragma unroll
    for (int it = 0; it < 8; it++) {
        int p = tid + it * 256;            // 2048
        int col = p & 63, m2 = p >> 6;
        float w0 = W2[(size_t)(2 * m2)     * 1024 + c * 256 + g * 64 + col];
        float w1 = W2[(size_t)(2 * m2 + 1) * 1024 + c * 256 + g * 64 + col];
        uint32_t hi, lo;
        split_pack(w0, w1, hi, lo);
        g_Bhi[k][t][col * 32 + m2] = hi;
        g_Blo[k][t][col * 32 + m2] = lo;
    }
}

// ============================================================================
// scan12: per-block sums + last-block does the exclusive scan of block sums.
// ============================================================================
__global__ __launch_bounds__(256)
void scan12_kernel(int n, int e)
{
    __shared__ int sd[256];
    __shared__ int s2[512];
    __shared__ int isLast;
    const int t = threadIdx.x;
    int i = blockIdx.x * 256 + t;
    sd[t] = (i < n) ? g_hist[i] : 0;
    __syncthreads();
    for (int s = 128; s > 0; s >>= 1) {
        if (t < s) sd[t] += sd[t + s];
        __syncthreads();
    }
    if (t == 0) {
        g_bsum[blockIdx.x] = sd[0];
        __threadfence();
        int old = atomicAdd(&g_done, 1);
        isLast = (old == (int)gridDim.x - 1);
    }
    __syncthreads();
    if (!isLast) return;

    // last block: exclusive scan of g_bsum[0..gridDim.x)
    const int nb = gridDim.x;              // <= 512
    s2[t]       = (t < nb)       ? g_bsum[t]       : 0;
    s2[t + 256] = (t + 256 < nb) ? g_bsum[t + 256] : 0;
    __syncthreads();
    for (int off = 1; off < 512; off <<= 1) {
        int a0 = s2[t],       b0 = (t >= off)       ? s2[t - off]       : 0;
        int a1 = s2[t + 256], b1 = (t + 256 >= off) ? s2[t + 256 - off] : 0;
        __syncthreads();
        s2[t] = a0 + b0;
        s2[t + 256] = a1 + b1;
        __syncthreads();
    }
    if (t < nb)       g_bsum[t]       = (t == 0) ? 0 : s2[t - 1];
    if (t + 256 < nb) g_bsum[t + 256] = s2[t + 255];
    if (t == 0) { g_rowptr[n] = e; g_done = 0; }
}

// ============================================================================
// scan3: block-local exclusive scan + base -> rowptr/pos; self-zeroes g_hist.
// ============================================================================
__global__ __launch_bounds__(256)
void scan3_kernel(int n)
{
    __shared__ int sd[256];
    int i = blockIdx.x * 256 + threadIdx.x, t = threadIdx.x;
    int hv = (i < n) ? g_hist[i] : 0;
    if (i < n) g_hist[i] = 0;              // ready for next run's histogram
    sd[t] = hv;
    __syncthreads();
    for (int off = 1; off < 256; off <<= 1) {
        int v = sd[t];
        int add = (t >= off) ? sd[t - off] : 0;
        __syncthreads();
        sd[t] = v + add;
        __syncthreads();
    }
    if (i < n) {
        int r = g_bsum[blockIdx.x] + ((t == 0) ? 0 : sd[t - 1]);
        g_rowptr[i] = r;
        g_pos[i] = r;
    }
}

// ============================================================================
// gather: 1 warp per node; half-warp per edge, l16 lanes own float4.
// Writes MEANS (1/deg folded) to g_acc; no atomics, no g_cnt.
// ============================================================================
__global__ __launch_bounds__(256)
void gather_kernel(int n)
{
    int w = (blockIdx.x * 256 + threadIdx.x) >> 5;
    int lane = threadIdx.x & 31;
    if (w >= n) return;
    int beg = g_rowptr[w], end = g_rowptr[w + 1];
    int half = lane >> 4, l16 = lane & 15;
    float4 a = make_float4(0.f, 0.f, 0.f, 0.f);
    for (int j = beg + half; j < end; j += 2) {
        int s = g_eidx[j];
        float4 v = *(const float4*)&g_kyv[(size_t)s * 64 + l16 * 4];
        a.x += v.x; a.y += v.y; a.z += v.z; a.w += v.w;
    }
    a.x += __shfl_down_sync(0xFFFFFFFFu, a.x, 16);
    a.y += __shfl_down_sync(0xFFFFFFFFu, a.y, 16);
    a.z += __shfl_down_sync(0xFFFFFFFFu, a.z, 16);
    a.w += __shfl_down_sync(0xFFFFFFFFu, a.w, 16);
    if (half == 0) {
        float inv = 1.0f / fmaxf((float)(end - beg), 1.0f);
        *(float4*)&g_acc[(size_t)w * 64 + l16 * 4] =
            make_float4(a.x * inv, a.y * inv, a.z * inv, a.w * inv);
    }
}

// ============================================================================
// Fused node kernel (proven mainloop).  K1's launch carries FILLB leading
// blocks doing the CSR slot-fill.  K2 tail: v -> bf16 hi/lo in dead A region,
// mW^T tile -> O_BUF, one verified 3-pass MMA group -> out (+mb).
// ============================================================================
template<int IS_K2>
__global__ __launch_bounds__(256, 2)
void node_kernel(const float* __restrict__ xin, const float* __restrict__ ea,
                 const float* __restrict__ W1, const float* __restrict__ b1,
                 const float* __restrict__ b2,
                 const float* __restrict__ mb,
                 const int* __restrict__ ei, int e,
                 float* __restrict__ out, int n)
{
    // ---- K1-only: CSR fill in leading blocks (depends on scan3, done) ----
    if (!IS_K2 && blockIdx.x < FILLB) {
        for (int i = blockIdx.x * 256 + threadIdx.x; i < e; i += FILLB * 256) {
            int dst = ei[i];
            int src = ei[e + i];
            int p = atomicAdd(&g_pos[dst], 1);
            g_eidx[p] = src;
        }
        return;
    }

    extern __shared__ __align__(16) char sm[];
    const uint32_t smb = smem_u32(sm);
    const int tid = threadIdx.x, wid = tid >> 5, lane = tid & 31;
    const int nb = (IS_K2 ? blockIdx.x : (blockIdx.x - FILLB)) * TILE;

    // ---- stage A: h = relu(ea@W1+b1) hi/lo bf16, [node][m], row 144B ----
    {
        const int node = tid >> 1, mh = tid & 1;
        const bool ok = (nb + node) < n;
        float e0 = 0.f, e1 = 0.f, e2 = 0.f;
        if (ok) { const float* ep = ea + (size_t)(nb + node) * 3; e0 = ep[0]; e1 = ep[1]; e2 = ep[2]; }
        #pragma unroll
        for (int mm = 0; mm < 16; mm++) {
            int m = mh * 32 + mm * 2;
            float h0 = 0.f, h1 = 0.f;
            if (ok) {
                h0 = fmaxf(fmaf(e2, W1[128 + m],     fmaf(e1, W1[64 + m],     fmaf(e0, W1[m],     b1[m]))),     0.f);
                h1 = fmaxf(fmaf(e2, W1[128 + m + 1], fmaf(e1, W1[64 + m + 1], fmaf(e0, W1[m + 1], b1[m + 1]))), 0.f);
            }
            uint32_t hiw, low;
            split_pack(h0, h1, hiw, low);
            uint32_t off = (uint32_t)(node * 144 + m * 2);
            *(uint32_t*)(sm + O_AHI + off) = hiw;
            *(uint32_t*)(sm + O_ALO + off) = low;
        }
    }
    // ---- stage full b2 (1024 f32) once ----
    ((float4*)(sm + O_B2))[tid] = ((const float4*)b2)[tid];
    __syncthreads();                               // A + b2 staged

    // ---- load A fragments ONCE (A smem region dead afterwards) ----
    const uint32_t aRow = (uint32_t)((wid * 16 + (lane & 15)) * 144 + ((lane >> 4) * 16));
    uint32_t ah[4][4], al[4][4];
    #pragma unroll
    for (int ks = 0; ks < 4; ks++) {
        lda4(ah[ks], smb + O_AHI + aRow + ks * 32);
        lda4(al[ks], smb + O_ALO + aRow + ks * 32);
    }

    // x4 B addressing: lanes 16-31 take the next ct tile (+8 rows = +1152B)
    const uint32_t bRow4 = (uint32_t)((lane & 7) * 144 + (((lane >> 3) & 1) * 16)
                                      + ((lane >> 4) * 1152));
    const int r0   = wid * 16 + (lane >> 2);       // C frag rows r0, r0+8
    const int colq = 2 * (lane & 3);

    const int row0 = nb + r0, row1 = nb + r0 + 8;
    const bool v0 = row0 < n, v1 = row1 < n;
    const float* src = IS_K2 ? g_acc : xin;

    // per-thread cp.async slots (same tile mapping as prep layout)
    const uint32_t st_off0 = (uint32_t)((tid >> 3) * 144 + (tid & 7) * 16);
    const uint32_t st_off1 = (uint32_t)(((tid + 256) >> 3) * 144 + (tid & 7) * 16);

    // ---- prologue: stage tile q=0 into buf 0 ----
    {
        const char* sH = (const char*)g_Bhi[IS_K2][0];
        const char* sL = (const char*)g_Blo[IS_K2][0];
        uint32_t dH = smb + O_BUF;
        cp16(dH + st_off0,        sH + (size_t)tid * 16);
        cp16(dH + 9216 + st_off0, sL + (size_t)tid * 16);
        cp16(dH + st_off1,        sH + (size_t)(tid + 256) * 16);
        cp16(dH + 9216 + st_off1, sL + (size_t)(tid + 256) * 16);
        CP_COMMIT();
    }

    const float* b2s = (const float*)(sm + O_B2);

    for (int c = 0; c < 4; c++) {
        float y[8] = {0.f, 0.f, 0.f, 0.f, 0.f, 0.f, 0.f, 0.f};

        for (int gg = 0; gg < 4; gg++) {
            const int q = c * 4 + gg;
            CP_WAIT0();
            __syncthreads();                       // buf q ready; buf q+1 free
            if (q < 15) {                          // async-stage next tile
                const char* sH = (const char*)g_Bhi[IS_K2][q + 1];
                const char* sL = (const char*)g_Blo[IS_K2][q + 1];
                uint32_t dH = smb + O_BUF + ((q + 1) & 1) * 18432;
                cp16(dH + st_off0,        sH + (size_t)tid * 16);
                cp16(dH + 9216 + st_off0, sL + (size_t)tid * 16);
                cp16(dH + st_off1,        sH + (size_t)(tid + 256) * 16);
                cp16(dH + 9216 + st_off1, sL + (size_t)(tid + 256) * 16);
                CP_COMMIT();
            }

            // x for phase B (load early; read-only data)
            float4 x0 = make_float4(0.f, 0.f, 0.f, 0.f), x1 = x0;
            if (v0) x0 = *(const float4*)&src[(size_t)row0 * 64 + c * 16 + gg * 4];
            if (v1) x1 = *(const float4*)&src[(size_t)row1 * 64 + c * 16 + gg * 4];
            float xk0a[4] = {x0.x, x0.y, x0.z, x0.w};
            float xk1a[4] = {x1.x, x1.y, x1.z, x1.w};

            const uint32_t bufb = smb + O_BUF + (uint32_t)((q & 1) * 18432);

            // ---- HMMA in two ct-halves (acc = 16 regs each) ----
            #pragma unroll
            for (int h = 0; h < 2; h++) {
                float acc[4][4];
                #pragma unroll
                for (int l = 0; l < 4; l++)
                    #pragma unroll
                    for (int p = 0; p < 4; p++) acc[l][p] = 0.f;
                #pragma unroll
                for (int ks = 0; ks < 4; ks++) {
                    #pragma unroll
                    for (int c2 = 0; c2 < 2; c2++) {
                        uint32_t bq[4];
                        ldb4(bq, bufb + (uint32_t)((h * 4 + c2 * 2) * 1152) + bRow4 + ks * 32);
                        mma16816(acc[c2 * 2],     ah[ks], bq);
                        mma16816(acc[c2 * 2 + 1], ah[ks], bq + 2);
                        mma16816(acc[c2 * 2],     al[ks], bq);
                        mma16816(acc[c2 * 2 + 1], al[ks], bq + 2);
                    }
                    #pragma unroll
                    for (int c2 = 0; c2 < 2; c2++) {
                        uint32_t bq[4];
                        ldb4(bq, bufb + 9216u + (uint32_t)((h * 4 + c2 * 2) * 1152) + bRow4 + ks * 32);
                        mma16816(acc[c2 * 2],     ah[ks], bq);
                        mma16816(acc[c2 * 2 + 1], ah[ks], bq + 2);
                    }
                }
                // ---- phase B for this half: ct = h*4+l ----
                #pragma unroll
                for (int l = 0; l < 4; l++) {
                    const int ct = h * 4 + l;
                    const int kl = ct >> 1;
                    const int jb = (ct & 1) * 2;
                    float2 bb = *(const float2*)&b2s[c * 256 + gg * 64 + ct * 8 + colq];
                    y[jb]         = fmaf(xk0a[kl], acc[l][0] + bb.x, y[jb]);
                    y[jb + 1]     = fmaf(xk0a[kl], acc[l][1] + bb.y, y[jb + 1]);
                    y[4 + jb]     = fmaf(xk1a[kl], acc[l][2] + bb.x, y[4 + jb]);
                    y[4 + jb + 1] = fmaf(xk1a[kl], acc[l][3] + bb.y, y[4 + jb + 1]);
                }
            }
        }

        if (!IS_K2) {
            if (v0) {
                *(float2*)&g_kyv[(size_t)row0 * 64 + c * 16 + colq]     = make_float2(y[0], y[1]);
                *(float2*)&g_kyv[(size_t)row0 * 64 + c * 16 + 8 + colq] = make_float2(y[2], y[3]);
            }
            if (v1) {
                *(float2*)&g_kyv[(size_t)row1 * 64 + c * 16 + colq]     = make_float2(y[4], y[5]);
                *(float2*)&g_kyv[(size_t)row1 * 64 + c * 16 + 8 + colq] = make_float2(y[6], y[7]);
            }
        } else {
            // v -> bf16 hi/lo in dead A regions, stage-A layout (mean already
            // folded into g_acc by gather)
            uint32_t hi, lo;
            uint32_t o0 = (uint32_t)(r0 * 144 + (c * 16 + colq) * 2);
            split_pack(y[0], y[1], hi, lo);
            *(uint32_t*)(sm + O_AHI + o0) = hi;  *(uint32_t*)(sm + O_ALO + o0) = lo;
            uint32_t o1 = (uint32_t)(r0 * 144 + (c * 16 + 8 + colq) * 2);
            split_pack(y[2], y[3], hi, lo);
            *(uint32_t*)(sm + O_AHI + o1) = hi;  *(uint32_t*)(sm + O_ALO + o1) = lo;
            uint32_t o2 = (uint32_t)((r0 + 8) * 144 + (c * 16 + colq) * 2);
            split_pack(y[4], y[5], hi, lo);
            *(uint32_t*)(sm + O_AHI + o2) = hi;  *(uint32_t*)(sm + O_ALO + o2) = lo;
            uint32_t o3 = (uint32_t)((r0 + 8) * 144 + (c * 16 + 8 + colq) * 2);
            split_pack(y[6], y[7], hi, lo);
            *(uint32_t*)(sm + O_AHI + o3) = hi;  *(uint32_t*)(sm + O_ALO + o3) = lo;
        }
    }

    // ---- K2 tail: out = v @ mW^T + mb via ONE verified MMA group ----
    if (IS_K2) {
        __syncthreads();                           // all v bf16 writes visible
        {
            uint32_t dH = smb + O_BUF;
            cp16(dH + st_off0,        (const char*)g_Mhi + (size_t)tid * 16);
            cp16(dH + 9216 + st_off0, (const char*)g_Mlo + (size_t)tid * 16);
            cp16(dH + st_off1,        (const char*)g_Mhi + (size_t)(tid + 256) * 16);
            cp16(dH + 9216 + st_off1, (const char*)g_Mlo + (size_t)(tid + 256) * 16);
            CP_COMMIT();
            CP_WAIT0();
        }
        __syncthreads();                           // mix B ready
        #pragma unroll
        for (int ks = 0; ks < 4; ks++) {
            lda4(ah[ks], smb + O_AHI + aRow + ks * 32);
            lda4(al[ks], smb + O_ALO + aRow + ks * 32);
        }
        const uint32_t bufb = smb + O_BUF;
        #pragma unroll
        for (int h = 0; h < 2; h++) {
            float acc[4][4];
            #pragma unroll
            for (int l = 0; l < 4; l++)
                #pragma unroll
                for (int p = 0; p < 4; p++) acc[l][p] = 0.f;
            #pragma unroll
            for (int ks = 0; ks < 4; ks++) {
                #pragma unroll
                for (int c2 = 0; c2 < 2; c2++) {
                    uint32_t bq[4];
                    ldb4(bq, bufb + (uint32_t)((h * 4 + c2 * 2) * 1152) + bRow4 + ks * 32);
                    mma16816(acc[c2 * 2],     ah[ks], bq);
                    mma16816(acc[c2 * 2 + 1], ah[ks], bq + 2);
                    mma16816(acc[c2 * 2],     al[ks], bq);
                    mma16816(acc[c2 * 2 + 1], al[ks], bq + 2);
                }
                #pragma unroll
                for (int c2 = 0; c2 < 2; c2++) {
                    uint32_t bq[4];
                    ldb4(bq, bufb + 9216u + (uint32_t)((h * 4 + c2 * 2) * 1152) + bRow4 + ks * 32);
                    mma16816(acc[c2 * 2],     ah[ks], bq);
                    mma16816(acc[c2 * 2 + 1], ah[ks], bq + 2);
                }
            }
            #pragma unroll
            for (int l = 0; l < 4; l++) {
                const int ct = h * 4 + l;
                float2 mbv = *(const float2*)&mb[ct * 8 + colq];
                if (v0) *(float2*)&out[(size_t)row0 * 64 + ct * 8 + colq] =
                            make_float2(acc[l][0] + mbv.x, acc[l][1] + mbv.y);
                if (v1) *(float2*)&out[(size_t)row1 * 64 + ct * 8 + colq] =
                            make_float2(acc[l][2] + mbv.x, acc[l][3] + mbv.y);
            }
        }
    }
}

// ============================================================================
extern "C" void kernel_launch(void* const* d_in, const int* in_sizes, int n_in,
                              void* d_out, int out_size)
{
    const float* x    = (const float*)d_in[0];
    const float* ea   = (const float*)d_in[1];
    const int*   ei   = (const int*)  d_in[2];
    const float* k1W1 = (const float*)d_in[3];
    const float* k1b1 = (const float*)d_in[4];
    const float* k1W2 = (const float*)d_in[5];
    const float* k1b2 = (const float*)d_in[6];
    const float* k2W1 = (const float*)d_in[7];
    const float* k2b1 = (const float*)d_in[8];
    const float* k2W2 = (const float*)d_in[9];
    const float* k2b2 = (const float*)d_in[10];
    const float* mW   = (const float*)d_in[11];
    const float* mb   = (const float*)d_in[12];
    float* out = (float*)d_out;

    const int n = in_sizes[0] / 64;        // 100000
    const int e = in_sizes[2] / 2;         // 3200000

    cudaFuncSetAttribute(node_kernel<0>, cudaFuncAttributeMaxDynamicSharedMemorySize, SMEM_SZ);
    cudaFuncSetAttribute(node_kernel<1>, cudaFuncAttributeMaxDynamicSharedMemorySize, SMEM_SZ);

    const int node_blocks = (n + TILE - 1) / TILE;
    const int nblk  = (n + 255) / 256;     // 391 for n=100000 (<=512 for scan12)
    const int eblk  = (e + 255) / 256;
    const int gblk  = (n * 32 + 255) / 256;

    // prep (W2/mix packing) + edge histogram, one launch
    prep_hist_kernel<<<33 + eblk, 256>>>(k1W2, k2W2, mW, ei, e);
    // block sums + last-block exclusive scan of sums
    scan12_kernel<<<nblk, 256>>>(n, e);
    // per-node rowptr/pos (+ self-zero g_hist for next run)
    scan3_kernel<<<nblk, 256>>>(n);
    // K1: ky_v  (+ FILLB leading blocks doing CSR fill, overlapped)
    node_kernel<0><<<node_blocks + FILLB, 256, SMEM_SZ>>>(x, ea, k1W1, k1b1, k1b2,
                                                          nullptr, ei, e, nullptr, n);
    // atomic-free gather-reduce (means, 1/deg folded)
    gather_kernel<<<gblk, 256>>>(n);
    // K2 + HMMA mix tail
    node_kernel<1><<<node_blocks, 256, SMEM_SZ>>>(nullptr, ea, k2W1, k2b1, k2b2,
                                                  mb, nullptr, 0, out, n);
}